// round 4
// baseline (speedup 1.0000x reference)
#include <cuda_runtime.h>
#include <math.h>

// Scratch for the per-query MLP weights (N x cols). 4096*80 floats = 1.25 MB.
__device__ float g_weights[4096 * 80];

// ---------------------------------------------------------------------------
// f32x2 packed helpers (sm_100+)
// ---------------------------------------------------------------------------
__device__ __forceinline__ unsigned long long pack2(float lo, float hi) {
    unsigned long long r;
    asm("mov.b64 %0, {%1, %2};" : "=l"(r) : "f"(lo), "f"(hi));
    return r;
}

__device__ __forceinline__ void fma2(unsigned long long& acc,
                                     unsigned long long a,
                                     unsigned long long b) {
    asm("fma.rn.f32x2 %0, %1, %2, %0;" : "+l"(acc) : "l"(a), "l"(b));
}

// acc = relu(x2*w10 + ay) * w2
__device__ __forceinline__ void fma2_relu_init(unsigned long long& acc,
                                               unsigned long long x2,
                                               unsigned long long w10,
                                               unsigned long long ay,
                                               unsigned long long w2) {
    asm("{\n\t"
        ".reg .b32 lo, hi;\n\t"
        ".reg .b64 p, r;\n\t"
        "fma.rn.f32x2 p, %1, %2, %3;\n\t"
        "mov.b64 {lo, hi}, p;\n\t"
        "max.f32 lo, lo, 0f00000000;\n\t"
        "max.f32 hi, hi, 0f00000000;\n\t"
        "mov.b64 r, {lo, hi};\n\t"
        "mul.rn.f32x2 %0, r, %4;\n\t"
        "}"
        : "=l"(acc)
        : "l"(x2), "l"(w10), "l"(ay), "l"(w2));
}

// acc += relu(x2*w10 + ay) * w2
__device__ __forceinline__ void fma2_relu_acc(unsigned long long& acc,
                                              unsigned long long x2,
                                              unsigned long long w10,
                                              unsigned long long ay,
                                              unsigned long long w2) {
    asm("{\n\t"
        ".reg .b32 lo, hi;\n\t"
        ".reg .b64 p, r;\n\t"
        "fma.rn.f32x2 p, %1, %2, %3;\n\t"
        "mov.b64 {lo, hi}, p;\n\t"
        "max.f32 lo, lo, 0f00000000;\n\t"
        "max.f32 hi, hi, 0f00000000;\n\t"
        "mov.b64 r, {lo, hi};\n\t"
        "fma.rn.f32x2 %0, r, %4, %0;\n\t"
        "}"
        : "+l"(acc)
        : "l"(x2), "l"(w10), "l"(ay), "l"(w2));
}

__device__ __forceinline__ float hsum2_plus(unsigned long long acc, float b2) {
    float lo, hi;
    asm("mov.b64 {%0, %1}, %2;" : "=f"(lo), "=f"(hi) : "l"(acc));
    return (lo + hi) + b2;
}

__device__ __forceinline__ void unpack2(unsigned long long v, float& lo, float& hi) {
    asm("mov.b64 {%0, %1}, %2;" : "=f"(lo), "=f"(hi) : "l"(v));
}

// ---------------------------------------------------------------------------
// GEMM kernel (fast path, dim=256, cols=65): weights = q @ Wg + bg.
// Grid = N/16 CTAs, 128 threads. Warp w handles 4 n's; lane owns packed
// column pair (2*lane, 2*lane+1); col 64 accumulated uniformly (broadcast
// load), stored by lane 31. q rows staged in smem via float4.
// Wg read coalesced: total Wg traffic = 150 x 66KB = 10 MB (vs 160 MB fused).
// ---------------------------------------------------------------------------
__global__ void __launch_bounds__(128)
posmlp_gemm16_kernel(const float* __restrict__ q,
                     const float* __restrict__ Wg,
                     const float* __restrict__ bg,
                     float* __restrict__ w_out) {
    const int n0   = blockIdx.x * 16;
    const int tid  = threadIdx.x;
    const int wid  = tid >> 5;
    const int lane = tid & 31;

    __shared__ float sq[16 * 256];
    {
        const float4* src = reinterpret_cast<const float4*>(q + (size_t)n0 * 256);
        float4* dst = reinterpret_cast<float4*>(sq);
        #pragma unroll
        for (int i = 0; i < 8; i++) dst[tid + i * 128] = src[tid + i * 128];
    }
    __syncthreads();

    const int c = 2 * lane;
    const float* sqw = sq + wid * 4 * 256;

    unsigned long long acc0 = pack2(0.f, 0.f), acc1 = acc0, acc2 = acc0, acc3 = acc0;
    float a64_0 = 0.f, a64_1 = 0.f, a64_2 = 0.f, a64_3 = 0.f;

    #pragma unroll 4
    for (int d = 0; d < 256; d++) {
        const float* wrow = Wg + (size_t)d * 65;
        const unsigned long long wp = pack2(wrow[c], wrow[c + 1]);
        const float w64 = wrow[64];   // broadcast: one line for whole warp

        const float q0 = sqw[d];
        const float q1 = sqw[256 + d];
        const float q2 = sqw[512 + d];
        const float q3 = sqw[768 + d];

        fma2(acc0, pack2(q0, q0), wp);  a64_0 = fmaf(q0, w64, a64_0);
        fma2(acc1, pack2(q1, q1), wp);  a64_1 = fmaf(q1, w64, a64_1);
        fma2(acc2, pack2(q2, q2), wp);  a64_2 = fmaf(q2, w64, a64_2);
        fma2(acc3, pack2(q3, q3), wp);  a64_3 = fmaf(q3, w64, a64_3);
    }

    const float bgc0 = bg[c];
    const float bgc1 = bg[c + 1];
    const float bg64 = bg[64];

    const int nbase = n0 + wid * 4;
    float lo, hi;
    unpack2(acc0, lo, hi);
    w_out[(size_t)(nbase + 0) * 65 + c]     = lo + bgc0;
    w_out[(size_t)(nbase + 0) * 65 + c + 1] = hi + bgc1;
    unpack2(acc1, lo, hi);
    w_out[(size_t)(nbase + 1) * 65 + c]     = lo + bgc0;
    w_out[(size_t)(nbase + 1) * 65 + c + 1] = hi + bgc1;
    unpack2(acc2, lo, hi);
    w_out[(size_t)(nbase + 2) * 65 + c]     = lo + bgc0;
    w_out[(size_t)(nbase + 2) * 65 + c + 1] = hi + bgc1;
    unpack2(acc3, lo, hi);
    w_out[(size_t)(nbase + 3) * 65 + c]     = lo + bgc0;
    w_out[(size_t)(nbase + 3) * 65 + c + 1] = hi + bgc1;

    if (lane == 31) {
        w_out[(size_t)(nbase + 0) * 65 + 64] = a64_0 + bg64;
        w_out[(size_t)(nbase + 1) * 65 + 64] = a64_1 + bg64;
        w_out[(size_t)(nbase + 2) * 65 + 64] = a64_2 + bg64;
        w_out[(size_t)(nbase + 3) * 65 + 64] = a64_3 + bg64;
    }
}

// ---------------------------------------------------------------------------
// Main kernel (H=W=64, hidden=16): one CTA per n, 128 threads.
// Thread t: row y=t>>1, 32 x's from (t&1)*32. Weights read from scratch
// (65 floats) into smem then packed into 24 register pairs. 4 independent
// pixel chains, FFMA2 inner loop, float4 stores.
// ---------------------------------------------------------------------------
__global__ void __launch_bounds__(128, 6)
posmlp_main64_kernel(const float* __restrict__ pos,
                     const float* __restrict__ wts,
                     float* __restrict__ out) {
    const int n   = blockIdx.x;
    const int tid = threadIdx.x;

    __shared__ float sw[65];
    if (tid < 65) sw[tid] = wts[(size_t)n * 65 + tid];
    __syncthreads();

    const float cx = pos[(size_t)n * 4 + 0];
    const float cy = pos[(size_t)n * 4 + 1];
    const float bw = pos[(size_t)n * 4 + 2];
    const float bh = pos[(size_t)n * 4 + 3];
    const float inv_bw = 1.0f / bw;
    const float inv_bh = 1.0f / bh;

    const int y  = tid >> 1;
    const int x0 = (tid & 1) * 32;

    const float rel_y = (((float)y + 0.5f) * (1.0f / 64.0f) - cy) * inv_bh;

    unsigned long long w10p[8], ayp[8], w2p[8];
    #pragma unroll
    for (int k2 = 0; k2 < 8; k2++) {
        const int k = 2 * k2;
        w10p[k2] = pack2(sw[k], sw[k + 1]);
        ayp[k2]  = pack2(fmaf(rel_y, sw[16 + k],     sw[32 + k]),
                         fmaf(rel_y, sw[16 + k + 1], sw[32 + k + 1]));
        w2p[k2]  = pack2(sw[48 + k], sw[48 + k + 1]);
    }
    const float b2 = sw[64];

    const float sx = inv_bw * (1.0f / 64.0f);
    const float tx = (0.5f * (1.0f / 64.0f) - cx) * inv_bw;

    float* orow = out + (((size_t)n * 64 + y) * 64 + x0);

    #pragma unroll
    for (int xi = 0; xi < 32; xi += 4) {
        unsigned long long x2a, x2b, x2c, x2d;
        {
            const float ra = fmaf((float)(x0 + xi + 0), sx, tx);
            const float rb = fmaf((float)(x0 + xi + 1), sx, tx);
            const float rc = fmaf((float)(x0 + xi + 2), sx, tx);
            const float rd = fmaf((float)(x0 + xi + 3), sx, tx);
            x2a = pack2(ra, ra);
            x2b = pack2(rb, rb);
            x2c = pack2(rc, rc);
            x2d = pack2(rd, rd);
        }

        unsigned long long aa, ab, ac, ad;
        fma2_relu_init(aa, x2a, w10p[0], ayp[0], w2p[0]);
        fma2_relu_init(ab, x2b, w10p[0], ayp[0], w2p[0]);
        fma2_relu_init(ac, x2c, w10p[0], ayp[0], w2p[0]);
        fma2_relu_init(ad, x2d, w10p[0], ayp[0], w2p[0]);
        #pragma unroll
        for (int k2 = 1; k2 < 8; k2++) {
            fma2_relu_acc(aa, x2a, w10p[k2], ayp[k2], w2p[k2]);
            fma2_relu_acc(ab, x2b, w10p[k2], ayp[k2], w2p[k2]);
            fma2_relu_acc(ac, x2c, w10p[k2], ayp[k2], w2p[k2]);
            fma2_relu_acc(ad, x2d, w10p[k2], ayp[k2], w2p[k2]);
        }

        float4 res;
        res.x = hsum2_plus(aa, b2);
        res.y = hsum2_plus(ab, b2);
        res.z = hsum2_plus(ac, b2);
        res.w = hsum2_plus(ad, b2);
        *reinterpret_cast<float4*>(orow + xi) = res;
    }
}

// ---------------------------------------------------------------------------
// Fallback path (other shapes).
// ---------------------------------------------------------------------------
__global__ void posmlp_gemm_kernel(const float* __restrict__ q,
                                   const float* __restrict__ Wg,
                                   const float* __restrict__ bg,
                                   float* __restrict__ w_out,
                                   int dim, int cols) {
    extern __shared__ float sq[];
    const int n = blockIdx.x;
    const float* qr = q + (size_t)n * dim;
    for (int d = threadIdx.x; d < dim; d += blockDim.x) sq[d] = qr[d];
    __syncthreads();
    for (int j = threadIdx.x; j < cols; j += blockDim.x) {
        float acc = bg[j];
        #pragma unroll 8
        for (int d = 0; d < dim; d++) {
            acc = fmaf(sq[d], Wg[(size_t)d * cols + j], acc);
        }
        w_out[(size_t)n * cols + j] = acc;
    }
}

__global__ void posmlp_generic_kernel(const float* __restrict__ pos,
                                      const float* __restrict__ wts,
                                      float* __restrict__ out,
                                      int H, int W, int h, int cols) {
    const int n = blockIdx.x;
    const float* w = wts + (size_t)n * cols;
    const float cx = pos[(size_t)n * 4 + 0];
    const float cy = pos[(size_t)n * 4 + 1];
    const float bw = pos[(size_t)n * 4 + 2];
    const float bh = pos[(size_t)n * 4 + 3];
    const float b2 = w[4 * h];
    const int total = H * W;
    for (int idx = threadIdx.x; idx < total; idx += blockDim.x) {
        const int yy = idx / W;
        const int xx = idx - yy * W;
        const float rel_x = (((float)xx + 0.5f) / (float)W - cx) / bw;
        const float rel_y = (((float)yy + 0.5f) / (float)H - cy) / bh;
        float acc = b2;
        for (int k = 0; k < h; k++) {
            float pre = fmaf(rel_x, w[k], fmaf(rel_y, w[h + k], w[2 * h + k]));
            acc = fmaf(fmaxf(pre, 0.0f), w[3 * h + k], acc);
        }
        out[(size_t)n * total + idx] = acc;
    }
}

extern "C" void kernel_launch(void* const* d_in, const int* in_sizes, int n_in,
                              void* d_out, int out_size) {
    const float* pos = (const float*)d_in[0];
    const float* q   = (const float*)d_in[1];
    const float* Wg  = (const float*)d_in[2];
    const float* bg  = (const float*)d_in[3];
    float* out = (float*)d_out;

    const int N    = in_sizes[0] / 4;          // rows of pos
    const int dim  = in_sizes[1] / N;          // query dim
    const int cols = in_sizes[3];              // 4*h + 1
    const int HW   = out_size / N;
    const int H    = (int)(sqrt((double)HW) + 0.5);
    const int h    = (cols - 1) / 4;

    float* w_scratch;
    cudaGetSymbolAddress((void**)&w_scratch, g_weights);

    if (H == 64 && h == 16 && cols == 65 && dim == 256 && (N % 16) == 0) {
        posmlp_gemm16_kernel<<<N / 16, 128>>>(q, Wg, bg, w_scratch);
        posmlp_main64_kernel<<<N, 128>>>(pos, w_scratch, out);
    } else {
        posmlp_gemm_kernel<<<N, 256, dim * sizeof(float)>>>(q, Wg, bg, w_scratch, dim, cols);
        posmlp_generic_kernel<<<N, 256>>>(pos, w_scratch, out, H, H, h, cols);
    }
}

// round 5
// speedup vs baseline: 1.7124x; 1.7124x over previous
#include <cuda_runtime.h>
#include <math.h>

// Scratch for per-query MLP weights (N x cols). 4096*80 floats = 1.25 MB.
__device__ float g_weights[4096 * 80];

// ---------------------------------------------------------------------------
// f32x2 packed helpers (sm_100+)
// ---------------------------------------------------------------------------
__device__ __forceinline__ unsigned long long pack2(float lo, float hi) {
    unsigned long long r;
    asm("mov.b64 %0, {%1, %2};" : "=l"(r) : "f"(lo), "f"(hi));
    return r;
}

__device__ __forceinline__ unsigned long long add2(unsigned long long a,
                                                   unsigned long long b) {
    unsigned long long d;
    asm("add.rn.f32x2 %0, %1, %2;" : "=l"(d) : "l"(a), "l"(b));
    return d;
}

// acc = |x2*w10 + ay| * w2h        (packed pair of hidden units)
__device__ __forceinline__ void fma2_abs_init(unsigned long long& acc,
                                              unsigned long long x2,
                                              unsigned long long w10,
                                              unsigned long long ay,
                                              unsigned long long w2h) {
    asm("{\n\t"
        ".reg .b32 lo, hi;\n\t"
        ".reg .b64 p, r;\n\t"
        "fma.rn.f32x2 p, %1, %2, %3;\n\t"
        "mov.b64 {lo, hi}, p;\n\t"
        "abs.f32 lo, lo;\n\t"
        "abs.f32 hi, hi;\n\t"
        "mov.b64 r, {lo, hi};\n\t"
        "mul.rn.f32x2 %0, r, %4;\n\t"
        "}"
        : "=l"(acc)
        : "l"(x2), "l"(w10), "l"(ay), "l"(w2h));
}

// acc += |x2*w10 + ay| * w2h
__device__ __forceinline__ void fma2_abs_acc(unsigned long long& acc,
                                             unsigned long long x2,
                                             unsigned long long w10,
                                             unsigned long long ay,
                                             unsigned long long w2h) {
    asm("{\n\t"
        ".reg .b32 lo, hi;\n\t"
        ".reg .b64 p, r;\n\t"
        "fma.rn.f32x2 p, %1, %2, %3;\n\t"
        "mov.b64 {lo, hi}, p;\n\t"
        "abs.f32 lo, lo;\n\t"
        "abs.f32 hi, hi;\n\t"
        "mov.b64 r, {lo, hi};\n\t"
        "fma.rn.f32x2 %0, r, %4, %0;\n\t"
        "}"
        : "+l"(acc)
        : "l"(x2), "l"(w10), "l"(ay), "l"(w2h));
}

__device__ __forceinline__ void unpack2(unsigned long long v, float& lo, float& hi) {
    asm("mov.b64 {%0, %1}, %2;" : "=f"(lo), "=f"(hi) : "l"(v));
}

// ---------------------------------------------------------------------------
// GEMM (fast path, dim=256, cols=65): weights = q @ Wg + bg.
// Grid = N/16 CTAs x 256 threads. Wg staged to smem ONCE per CTA (stride
// padded 65->66 so LDS.64 stays aligned + conflict-free). 16 q rows in smem.
// Warp w handles n = 2w, 2w+1; lane owns column pair (2*lane, 2*lane+1);
// column 64 accumulated uniformly (broadcast), stored by lane 0.
// Wg L2 traffic: 150 x 66KB = 10 MB (vs 80 MB in round 4).
// ---------------------------------------------------------------------------
__global__ void __launch_bounds__(256)
posmlp_gemm_smem_kernel(const float* __restrict__ q,
                        const float* __restrict__ Wg,
                        const float* __restrict__ bg,
                        float* __restrict__ w_out) {
    extern __shared__ float smem[];
    float* swg = smem;              // 256 * 66 floats
    float* sq  = smem + 256 * 66;   // 16 * 256 floats

    const int n0   = blockIdx.x * 16;
    const int tid  = threadIdx.x;
    const int wid  = tid >> 5;
    const int lane = tid & 31;

    // Stage Wg (coalesced LDG, padded STS)
    #pragma unroll 5
    for (int i = tid; i < 256 * 65; i += 256) {
        const int d = i / 65;
        const int c = i - d * 65;
        swg[d * 66 + c] = Wg[i];
    }
    // Stage 16 q rows (float4)
    {
        const float4* src = reinterpret_cast<const float4*>(q + (size_t)n0 * 256);
        float4* dst = reinterpret_cast<float4*>(sq);
        #pragma unroll
        for (int i = 0; i < 4; i++) dst[tid + i * 256] = src[tid + i * 256];
    }
    __syncthreads();

    const int c = 2 * lane;
    const float* q0r = sq + (2 * wid + 0) * 256;
    const float* q1r = sq + (2 * wid + 1) * 256;

    float a0lo = 0.f, a0hi = 0.f, a1lo = 0.f, a1hi = 0.f;
    float a64_0 = 0.f, a64_1 = 0.f;

    #pragma unroll 8
    for (int d = 0; d < 256; d++) {
        const float2 wv = *reinterpret_cast<const float2*>(&swg[d * 66 + c]);
        const float w64 = swg[d * 66 + 64];
        const float q0 = q0r[d];
        const float q1 = q1r[d];
        a0lo = fmaf(q0, wv.x, a0lo);
        a0hi = fmaf(q0, wv.y, a0hi);
        a64_0 = fmaf(q0, w64, a64_0);
        a1lo = fmaf(q1, wv.x, a1lo);
        a1hi = fmaf(q1, wv.y, a1hi);
        a64_1 = fmaf(q1, w64, a64_1);
    }

    const float bgc0 = bg[c];
    const float bgc1 = bg[c + 1];

    const int na = n0 + 2 * wid;
    w_out[(size_t)na * 65 + c]           = a0lo + bgc0;
    w_out[(size_t)na * 65 + c + 1]       = a0hi + bgc1;
    w_out[(size_t)(na + 1) * 65 + c]     = a1lo + bgc0;
    w_out[(size_t)(na + 1) * 65 + c + 1] = a1hi + bgc1;
    if (lane == 0) {
        const float bg64 = bg[64];
        w_out[(size_t)na * 65 + 64]       = a64_0 + bg64;
        w_out[(size_t)(na + 1) * 65 + 64] = a64_1 + bg64;
    }
}

// ---------------------------------------------------------------------------
// Main kernel (H=W=64, hidden=16): one CTA per n, 128 threads.
// relu(p)*w2 = 0.5*p*w2 + 0.5*|p|*w2. Linear half folded into per-thread
// (LA, LB): out(x) = LA*rel_x + LBb2 + sum_k |p_k| * (0.5*w2_k).
// Inner loop: 16 FFMA2 per pixel (abs folds into the FFMA2 source in SASS),
// zero alu-pipe ReLU work. 4 independent pixel chains; float4 stores.
// ---------------------------------------------------------------------------
__global__ void __launch_bounds__(128, 6)
posmlp_main64_kernel(const float* __restrict__ pos,
                     const float* __restrict__ wts,
                     float* __restrict__ out) {
    const int n   = blockIdx.x;
    const int tid = threadIdx.x;

    __shared__ float sw[65];
    if (tid < 65) sw[tid] = wts[(size_t)n * 65 + tid];
    __syncthreads();

    const float cx = pos[(size_t)n * 4 + 0];
    const float cy = pos[(size_t)n * 4 + 1];
    const float bw = pos[(size_t)n * 4 + 2];
    const float bh = pos[(size_t)n * 4 + 3];
    const float inv_bw = 1.0f / bw;
    const float inv_bh = 1.0f / bh;

    const int y  = tid >> 1;
    const int x0 = (tid & 1) * 32;

    const float rel_y = (((float)y + 0.5f) * (1.0f / 64.0f) - cy) * inv_bh;

    unsigned long long w10p[8], ayp[8], w2hp[8];
    float LA = 0.f, LB = 0.f;
    #pragma unroll
    for (int k2 = 0; k2 < 8; k2++) {
        const int k = 2 * k2;
        const float w0 = sw[k],     w1 = sw[k + 1];
        const float a0 = fmaf(rel_y, sw[16 + k],     sw[32 + k]);
        const float a1 = fmaf(rel_y, sw[16 + k + 1], sw[32 + k + 1]);
        const float h0 = 0.5f * sw[48 + k];
        const float h1 = 0.5f * sw[48 + k + 1];
        LA = fmaf(w0, h0, LA); LA = fmaf(w1, h1, LA);
        LB = fmaf(a0, h0, LB); LB = fmaf(a1, h1, LB);
        w10p[k2] = pack2(w0, w1);
        ayp[k2]  = pack2(a0, a1);
        w2hp[k2] = pack2(h0, h1);
    }
    const float LBb2 = LB + sw[64];

    const float sx = inv_bw * (1.0f / 64.0f);
    const float tx = (0.5f * (1.0f / 64.0f) - cx) * inv_bw;

    // 4 independent packed rel_x chains, stepped by 4*sx each iteration
    const float r0 = fmaf((float)(x0 + 0), sx, tx);
    const float r1 = fmaf((float)(x0 + 1), sx, tx);
    const float r2 = fmaf((float)(x0 + 2), sx, tx);
    const float r3 = fmaf((float)(x0 + 3), sx, tx);
    unsigned long long x2a = pack2(r0, r0);
    unsigned long long x2b = pack2(r1, r1);
    unsigned long long x2c = pack2(r2, r2);
    unsigned long long x2d = pack2(r3, r3);
    const float sx4 = 4.0f * sx;
    const unsigned long long dx2 = pack2(sx4, sx4);

    float* orow = out + (((size_t)n * 64 + y) * 64 + x0);

    #pragma unroll
    for (int xi = 0; xi < 32; xi += 4) {
        unsigned long long aa, ab, ac, ad;
        fma2_abs_init(aa, x2a, w10p[0], ayp[0], w2hp[0]);
        fma2_abs_init(ab, x2b, w10p[0], ayp[0], w2hp[0]);
        fma2_abs_init(ac, x2c, w10p[0], ayp[0], w2hp[0]);
        fma2_abs_init(ad, x2d, w10p[0], ayp[0], w2hp[0]);
        #pragma unroll
        for (int k2 = 1; k2 < 8; k2++) {
            fma2_abs_acc(aa, x2a, w10p[k2], ayp[k2], w2hp[k2]);
            fma2_abs_acc(ab, x2b, w10p[k2], ayp[k2], w2hp[k2]);
            fma2_abs_acc(ac, x2c, w10p[k2], ayp[k2], w2hp[k2]);
            fma2_abs_acc(ad, x2d, w10p[k2], ayp[k2], w2hp[k2]);
        }

        float lo, hi, rxs, rdum;
        float4 res;
        unpack2(x2a, rxs, rdum);
        unpack2(aa, lo, hi);
        res.x = (lo + hi) + fmaf(rxs, LA, LBb2);
        unpack2(x2b, rxs, rdum);
        unpack2(ab, lo, hi);
        res.y = (lo + hi) + fmaf(rxs, LA, LBb2);
        unpack2(x2c, rxs, rdum);
        unpack2(ac, lo, hi);
        res.z = (lo + hi) + fmaf(rxs, LA, LBb2);
        unpack2(x2d, rxs, rdum);
        unpack2(ad, lo, hi);
        res.w = (lo + hi) + fmaf(rxs, LA, LBb2);
        *reinterpret_cast<float4*>(orow + xi) = res;

        x2a = add2(x2a, dx2);
        x2b = add2(x2b, dx2);
        x2c = add2(x2c, dx2);
        x2d = add2(x2d, dx2);
    }
}

// ---------------------------------------------------------------------------
// Fallback path (other shapes).
// ---------------------------------------------------------------------------
__global__ void posmlp_gemm_kernel(const float* __restrict__ q,
                                   const float* __restrict__ Wg,
                                   const float* __restrict__ bg,
                                   float* __restrict__ w_out,
                                   int dim, int cols) {
    extern __shared__ float sqf[];
    const int n = blockIdx.x;
    const float* qr = q + (size_t)n * dim;
    for (int d = threadIdx.x; d < dim; d += blockDim.x) sqf[d] = qr[d];
    __syncthreads();
    for (int j = threadIdx.x; j < cols; j += blockDim.x) {
        float acc = bg[j];
        #pragma unroll 8
        for (int d = 0; d < dim; d++) {
            acc = fmaf(sqf[d], Wg[(size_t)d * cols + j], acc);
        }
        w_out[(size_t)n * cols + j] = acc;
    }
}

__global__ void posmlp_generic_kernel(const float* __restrict__ pos,
                                      const float* __restrict__ wts,
                                      float* __restrict__ out,
                                      int H, int W, int h, int cols) {
    const int n = blockIdx.x;
    const float* w = wts + (size_t)n * cols;
    const float cx = pos[(size_t)n * 4 + 0];
    const float cy = pos[(size_t)n * 4 + 1];
    const float bw = pos[(size_t)n * 4 + 2];
    const float bh = pos[(size_t)n * 4 + 3];
    const float b2 = w[4 * h];
    const int total = H * W;
    for (int idx = threadIdx.x; idx < total; idx += blockDim.x) {
        const int yy = idx / W;
        const int xx = idx - yy * W;
        const float rel_x = (((float)xx + 0.5f) / (float)W - cx) / bw;
        const float rel_y = (((float)yy + 0.5f) / (float)H - cy) / bh;
        float acc = b2;
        for (int k = 0; k < h; k++) {
            float pre = fmaf(rel_x, w[k], fmaf(rel_y, w[h + k], w[2 * h + k]));
            acc = fmaf(fmaxf(pre, 0.0f), w[3 * h + k], acc);
        }
        out[(size_t)n * total + idx] = acc;
    }
}

extern "C" void kernel_launch(void* const* d_in, const int* in_sizes, int n_in,
                              void* d_out, int out_size) {
    const float* pos = (const float*)d_in[0];
    const float* q   = (const float*)d_in[1];
    const float* Wg  = (const float*)d_in[2];
    const float* bg  = (const float*)d_in[3];
    float* out = (float*)d_out;

    const int N    = in_sizes[0] / 4;          // rows of pos
    const int dim  = in_sizes[1] / N;          // query dim
    const int cols = in_sizes[3];              // 4*h + 1
    const int HW   = out_size / N;
    const int H    = (int)(sqrt((double)HW) + 0.5);
    const int h    = (cols - 1) / 4;

    float* w_scratch;
    cudaGetSymbolAddress((void**)&w_scratch, g_weights);

    if (H == 64 && h == 16 && cols == 65 && dim == 256 && (N % 16) == 0) {
        const int smem_bytes = (256 * 66 + 16 * 256) * sizeof(float);  // ~84 KB
        cudaFuncSetAttribute(posmlp_gemm_smem_kernel,
                             cudaFuncAttributeMaxDynamicSharedMemorySize, smem_bytes);
        posmlp_gemm_smem_kernel<<<N / 16, 256, smem_bytes>>>(q, Wg, bg, w_scratch);
        posmlp_main64_kernel<<<N, 128>>>(pos, w_scratch, out);
    } else {
        posmlp_gemm_kernel<<<N, 256, dim * sizeof(float)>>>(q, Wg, bg, w_scratch, dim, cols);
        posmlp_generic_kernel<<<N, 256>>>(pos, w_scratch, out, H, H, h, cols);
    }
}